// round 1
// baseline (speedup 1.0000x reference)
#include <cuda_runtime.h>
#include <math.h>

#define BB   16
#define NN   32
#define TDIM 256
#define I1   512
#define I2   512
#define HH   256
#define EPS  1e-5f

// Scratch for intermediate activations (allocation-free: __device__ globals)
__device__ float g_h1[BB * NN * HH];        // [512, 256]   0.5 MB
__device__ float g_h2[BB * TDIM * HH];      // [4096, 256]  4 MB

// ---------------------------------------------------------------------------
// relu_gemm: O[M,256] = relu(X[M,K] @ W[K,256] + bias), K = 512
// Block tile: 32 rows x 256 cols, 256 threads (8 warps x 32 lanes).
// Warp w owns rows {w, w+8, w+16, w+24}; lane owns cols {lane + 32c}.
// ---------------------------------------------------------------------------
__global__ __launch_bounds__(256) void relu_gemm_kernel(
    const float* __restrict__ X, const float* __restrict__ W,
    const float* __restrict__ bias, float* __restrict__ O)
{
    const int K = 512;
    __shared__ float Xs[32][32];
    __shared__ float Ws[32][256];

    const int tid  = threadIdx.x;
    const int lane = tid & 31;
    const int w    = tid >> 5;
    const int m0   = blockIdx.x * 32;

    float acc[4][8];
#pragma unroll
    for (int r = 0; r < 4; r++)
#pragma unroll
        for (int c = 0; c < 8; c++) acc[r][c] = 0.f;

    for (int kc = 0; kc < K; kc += 32) {
        // Xs: 1024 floats / 256 threads = 4 each
#pragma unroll
        for (int i = 0; i < 4; i++) {
            int idx = tid + i * 256;
            int r = idx >> 5, k = idx & 31;
            Xs[r][k] = X[(size_t)(m0 + r) * K + kc + k];
        }
        // Ws: rows kc..kc+31 of W = 8192 contiguous floats = 2048 float4
        const float4* Wg = reinterpret_cast<const float4*>(W + (size_t)kc * 256);
        float4* Wv = reinterpret_cast<float4*>(&Ws[0][0]);
#pragma unroll
        for (int i = 0; i < 8; i++) Wv[tid + i * 256] = Wg[tid + i * 256];
        __syncthreads();

#pragma unroll
        for (int k = 0; k < 32; k++) {
            float a[4], bfrag[8];
#pragma unroll
            for (int r = 0; r < 4; r++) a[r] = Xs[w + r * 8][k];       // broadcast
#pragma unroll
            for (int c = 0; c < 8; c++) bfrag[c] = Ws[k][lane + c * 32]; // conflict-free
#pragma unroll
            for (int r = 0; r < 4; r++)
#pragma unroll
                for (int c = 0; c < 8; c++) acc[r][c] = fmaf(a[r], bfrag[c], acc[r][c]);
        }
        __syncthreads();
    }

#pragma unroll
    for (int r = 0; r < 4; r++) {
        int row = m0 + w + r * 8;
#pragma unroll
        for (int c = 0; c < 8; c++) {
            int j = lane + c * 32;
            O[(size_t)row * 256 + j] = fmaxf(acc[r][c] + bias[j], 0.f);
        }
    }
}

// ---------------------------------------------------------------------------
// Fused main kernel: per block = one (b,n) and a 64-row t-tile.
//   x_t = h1[b,n,:] * h2[b,t,:]     (Hadamard, never hits HBM)
//   xn  = LN(x_t) * g0 + be0        -> SMEM [64, 256]
//   y   = xn @ W3 + b3              (register-tiled, W3 chunked via SMEM)
//   out = relu(LN(y) * g1 + be1)
// 512 threads = 16 warps; warp w owns rows {w, w+16, w+32, w+48};
// lane owns cols {lane + 32c}. Row-wise LN reductions = warp shuffles.
// ---------------------------------------------------------------------------
__global__ __launch_bounds__(512) void fused_main_kernel(
    const float* __restrict__ W3, const float* __restrict__ b3,
    const float* __restrict__ g0, const float* __restrict__ be0,
    const float* __restrict__ g1, const float* __restrict__ be1,
    float* __restrict__ out)
{
    extern __shared__ float sm[];
    float* xn  = sm;                    // 64*256
    float* W3s = xn + 64 * 256;         // 32*256
    float* h1s = W3s + 32 * 256;        // 256
    float* b3s = h1s + 256;             // 256
    float* g0s = b3s + 256;             // 256
    float* e0s = g0s + 256;             // 256
    float* g1s = e0s + 256;             // 256
    float* e1s = g1s + 256;             // 256

    const int tid  = threadIdx.x;
    const int lane = tid & 31;
    const int w    = tid >> 5;          // 0..15
    const int bn   = blockIdx.x;        // 0..511  (b*NN + n)
    const int t0   = blockIdx.y * 64;
    const int b    = bn >> 5;           // bn / 32

    if (tid < 256) {
        h1s[tid] = g_h1[(size_t)bn * 256 + tid];
        b3s[tid] = b3[tid];
        g0s[tid] = g0[tid];  e0s[tid] = be0[tid];
        g1s[tid] = g1[tid];  e1s[tid] = be1[tid];
    }
    __syncthreads();

    // ---- Phase 1: Hadamard + LayerNorm -> xn in SMEM ----
#pragma unroll
    for (int r = 0; r < 4; r++) {
        const int t = w + r * 16;
        const float* h2row = g_h2 + ((size_t)b * TDIM + t0 + t) * HH;
        float x[8], s = 0.f, s2 = 0.f;
#pragma unroll
        for (int c = 0; c < 8; c++) {
            int j = lane + c * 32;
            float v = h1s[j] * h2row[j];
            x[c] = v; s += v; s2 += v * v;
        }
#pragma unroll
        for (int o = 16; o > 0; o >>= 1) {
            s  += __shfl_xor_sync(0xffffffffu, s,  o);
            s2 += __shfl_xor_sync(0xffffffffu, s2, o);
        }
        float mu  = s * (1.f / 256.f);
        float var = s2 * (1.f / 256.f) - mu * mu;
        float inv = rsqrtf(var + EPS);
#pragma unroll
        for (int c = 0; c < 8; c++) {
            int j = lane + c * 32;
            xn[t * 256 + j] = (x[c] - mu) * inv * g0s[j] + e0s[j];
        }
    }
    __syncthreads();

    // ---- Phase 2: GEMM [64,256] @ W3[256,256] ----
    float acc[4][8];
#pragma unroll
    for (int r = 0; r < 4; r++)
#pragma unroll
        for (int c = 0; c < 8; c++) acc[r][c] = 0.f;

    for (int kc = 0; kc < 256; kc += 32) {
        const float4* Wg = reinterpret_cast<const float4*>(W3 + (size_t)kc * 256);
        float4* Wv = reinterpret_cast<float4*>(W3s);
#pragma unroll
        for (int i = 0; i < 4; i++) Wv[tid + i * 512] = Wg[tid + i * 512];
        __syncthreads();

#pragma unroll
        for (int k = 0; k < 32; k++) {
            float a[4], bfrag[8];
#pragma unroll
            for (int r = 0; r < 4; r++) a[r] = xn[(w + r * 16) * 256 + kc + k]; // broadcast
#pragma unroll
            for (int c = 0; c < 8; c++) bfrag[c] = W3s[k * 256 + lane + c * 32]; // conflict-free
#pragma unroll
            for (int r = 0; r < 4; r++)
#pragma unroll
                for (int c = 0; c < 8; c++) acc[r][c] = fmaf(a[r], bfrag[c], acc[r][c]);
        }
        __syncthreads();
    }

    // ---- Phase 3: +b3, LayerNorm, ReLU, store ----
    const size_t outbase = ((size_t)bn * TDIM + t0) * HH;
#pragma unroll
    for (int r = 0; r < 4; r++) {
        const int t = w + r * 16;
        float y[8], s = 0.f, s2 = 0.f;
#pragma unroll
        for (int c = 0; c < 8; c++) {
            int j = lane + c * 32;
            float v = acc[r][c] + b3s[j];
            y[c] = v; s += v; s2 += v * v;
        }
#pragma unroll
        for (int o = 16; o > 0; o >>= 1) {
            s  += __shfl_xor_sync(0xffffffffu, s,  o);
            s2 += __shfl_xor_sync(0xffffffffu, s2, o);
        }
        float mu  = s * (1.f / 256.f);
        float var = s2 * (1.f / 256.f) - mu * mu;
        float inv = rsqrtf(var + EPS);
#pragma unroll
        for (int c = 0; c < 8; c++) {
            int j = lane + c * 32;
            float o2 = (y[c] - mu) * inv * g1s[j] + e1s[j];
            out[outbase + (size_t)t * HH + j] = fmaxf(o2, 0.f);
        }
    }
}

// ---------------------------------------------------------------------------
extern "C" void kernel_launch(void* const* d_in, const int* in_sizes, int n_in,
                              void* d_out, int out_size)
{
    const float* x1  = (const float*)d_in[0];
    const float* x2  = (const float*)d_in[1];
    const float* W1  = (const float*)d_in[2];
    const float* b1  = (const float*)d_in[3];
    const float* W2  = (const float*)d_in[4];
    const float* b2  = (const float*)d_in[5];
    const float* W3  = (const float*)d_in[6];
    const float* b3  = (const float*)d_in[7];
    const float* g0  = (const float*)d_in[8];
    const float* be0 = (const float*)d_in[9];
    const float* g1  = (const float*)d_in[10];
    const float* be1 = (const float*)d_in[11];
    float* out = (float*)d_out;

    float* h1;  cudaGetSymbolAddress((void**)&h1, g_h1);
    float* h2;  cudaGetSymbolAddress((void**)&h2, g_h2);

    // h1 = relu(x1 @ W1 + b1): M = 512
    relu_gemm_kernel<<<BB * NN / 32, 256>>>(x1, W1, b1, h1);
    // h2 = relu(x2 @ W2 + b2): M = 4096
    relu_gemm_kernel<<<BB * TDIM / 32, 256>>>(x2, W2, b2, h2);

    // Fused Hadamard + LN + GEMM + LN + ReLU
    const int smem_bytes = (64 * 256 + 32 * 256 + 6 * 256) * sizeof(float); // 104448
    static int attr_set = 0;
    if (!attr_set) {
        cudaFuncSetAttribute(fused_main_kernel,
                             cudaFuncAttributeMaxDynamicSharedMemorySize, smem_bytes);
        attr_set = 1;
    }
    dim3 grid(BB * NN, TDIM / 64);
    fused_main_kernel<<<grid, 512, smem_bytes>>>(W3, b3, g0, be0, g1, be1, out);
}

// round 3
// speedup vs baseline: 1.8240x; 1.8240x over previous
#include <cuda_runtime.h>
#include <cuda_bf16.h>
#include <cstdint>
#include <math.h>

#define BB   16
#define NN   32
#define TDIM 256
#define HH   256
#define EPS  1e-5f

// ---------------------------------------------------------------------------
// Scratch (__device__ globals; no allocation allowed)
// ---------------------------------------------------------------------------
__device__ float g_h1[BB * NN * HH];                 // [512, 256]
__device__ float g_h2[BB * TDIM * HH];               // [4096, 256]
__device__ __nv_bfloat16 g_Bhi[256 * 256];           // W3^T hi  [n][k]
__device__ __nv_bfloat16 g_Blo[256 * 256];           // W3^T lo  [n][k]

__device__ __forceinline__ uint32_t smem_u32(const void* p) {
    uint32_t a;
    asm("{ .reg .u64 t; cvta.to.shared.u64 t, %1; cvt.u32.u64 %0, t; }" : "=r"(a) : "l"(p));
    return a;
}
__device__ __forceinline__ uint32_t pack_bf16x2(float lo, float hi) {
    uint32_t r;
    asm("cvt.rn.bf16x2.f32 %0, %1, %2;" : "=r"(r) : "f"(hi), "f"(lo));
    return r;
}

#define LDMX4(r, addr) \
    asm volatile("ldmatrix.sync.aligned.m8n8.x4.shared.b16 {%0,%1,%2,%3}, [%4];" \
        : "=r"((r)[0]), "=r"((r)[1]), "=r"((r)[2]), "=r"((r)[3]) : "r"(addr))

#define MMA16816(cc, a, b0, b1) \
    asm volatile("mma.sync.aligned.m16n8k16.row.col.f32.bf16.bf16.f32 " \
        "{%0,%1,%2,%3}, {%4,%5,%6,%7}, {%8,%9}, {%0,%1,%2,%3};" \
        : "+f"((cc)[0]), "+f"((cc)[1]), "+f"((cc)[2]), "+f"((cc)[3]) \
        : "r"((a)[0]), "r"((a)[1]), "r"((a)[2]), "r"((a)[3]), "r"(b0), "r"(b1))

#define CP_ASYNC16(dst, src) \
    asm volatile("cp.async.cg.shared.global [%0], [%1], 16;" :: "r"(dst), "l"(src))
#define CP_COMMIT() asm volatile("cp.async.commit_group;" ::: "memory")
#define CP_WAIT0()  asm volatile("cp.async.wait_group 0;" ::: "memory")

// ---------------------------------------------------------------------------
// Prep: W3 [k=256][n=256] fp32 -> g_Bhi/g_Blo = W3^T bf16 [n][k] (hi/lo split)
// ---------------------------------------------------------------------------
__global__ void prep_w3_kernel(const float* __restrict__ W3) {
    int idx = blockIdx.x * 256 + threadIdx.x;   // idx = n*256 + k
    int n = idx >> 8, k = idx & 255;
    float w = W3[k * 256 + n];
    __nv_bfloat16 hi = __float2bfloat16(w);
    __nv_bfloat16 lo = __float2bfloat16(w - __bfloat162float(hi));
    g_Bhi[idx] = hi;
    g_Blo[idx] = lo;
}

// ---------------------------------------------------------------------------
// Prologue: h1 = relu(x1@W1+b1), h2 = relu(x2@W2+b2), one launch (fp32).
// ---------------------------------------------------------------------------
__global__ __launch_bounds__(256) void relu_gemm_both(
    const float* __restrict__ x1, const float* __restrict__ W1, const float* __restrict__ b1,
    const float* __restrict__ x2, const float* __restrict__ W2, const float* __restrict__ b2)
{
    const int K = 512;
    __shared__ float Xs[32][32];
    __shared__ float Ws[32 * 256];

    const bool is1 = (blockIdx.x < 16);
    const float* X    = is1 ? x1 : x2;
    const float* W    = is1 ? W1 : W2;
    const float* bias = is1 ? b1 : b2;
    float* O          = is1 ? g_h1 : g_h2;
    const int m0      = (is1 ? blockIdx.x : (blockIdx.x - 16)) * 32;

    const int tid  = threadIdx.x;
    const int lane = tid & 31;
    const int w    = tid >> 5;

    float acc[4][8];
#pragma unroll
    for (int r = 0; r < 4; r++)
#pragma unroll
        for (int c = 0; c < 8; c++) acc[r][c] = 0.f;

    const float4* Wsv = (const float4*)Ws;

    for (int kc = 0; kc < K; kc += 32) {
#pragma unroll
        for (int i = 0; i < 4; i++) {
            int idx = tid + i * 256;
            int r = idx >> 5, k = idx & 31;
            Xs[r][k] = X[(size_t)(m0 + r) * K + kc + k];
        }
        const float4* Wg = (const float4*)(W + (size_t)kc * 256);
        float4* Wv = (float4*)Ws;
#pragma unroll
        for (int i = 0; i < 8; i++) Wv[tid + i * 256] = Wg[tid + i * 256];
        __syncthreads();

#pragma unroll
        for (int k = 0; k < 32; k++) {
            float a[4];
#pragma unroll
            for (int r = 0; r < 4; r++) a[r] = Xs[w + r * 8][k];
            float4 bv0 = Wsv[k * 64 + lane * 2];
            float4 bv1 = Wsv[k * 64 + lane * 2 + 1];
#pragma unroll
            for (int r = 0; r < 4; r++) {
                acc[r][0] = fmaf(a[r], bv0.x, acc[r][0]);
                acc[r][1] = fmaf(a[r], bv0.y, acc[r][1]);
                acc[r][2] = fmaf(a[r], bv0.z, acc[r][2]);
                acc[r][3] = fmaf(a[r], bv0.w, acc[r][3]);
                acc[r][4] = fmaf(a[r], bv1.x, acc[r][4]);
                acc[r][5] = fmaf(a[r], bv1.y, acc[r][5]);
                acc[r][6] = fmaf(a[r], bv1.z, acc[r][6]);
                acc[r][7] = fmaf(a[r], bv1.w, acc[r][7]);
            }
        }
        __syncthreads();
    }

    float bv[8];
#pragma unroll
    for (int c = 0; c < 8; c++) bv[c] = bias[lane * 8 + c];
#pragma unroll
    for (int r = 0; r < 4; r++) {
        int row = m0 + w + r * 8;
        float4 o0, o1;
        o0.x = fmaxf(acc[r][0] + bv[0], 0.f); o0.y = fmaxf(acc[r][1] + bv[1], 0.f);
        o0.z = fmaxf(acc[r][2] + bv[2], 0.f); o0.w = fmaxf(acc[r][3] + bv[3], 0.f);
        o1.x = fmaxf(acc[r][4] + bv[4], 0.f); o1.y = fmaxf(acc[r][5] + bv[5], 0.f);
        o1.z = fmaxf(acc[r][6] + bv[6], 0.f); o1.w = fmaxf(acc[r][7] + bv[7], 0.f);
        float4* op = (float4*)(O + (size_t)row * 256 + lane * 8);
        op[0] = o0; op[1] = o1;
    }
}

// ---------------------------------------------------------------------------
// Fused main kernel (mma.sync bf16 hi/lo split).
// CTA: 128 t-rows x 256 cols, K=256. 512 threads = 16 warps (4m x 4n),
// warp tile 32x64. 12 k-chunks of 64: [AhBh x4][AlBh x4][AhBl x4].
// SMEM: Ah[128][264], Al[128][264] bf16; B double buf [256][72] bf16.
// ---------------------------------------------------------------------------
#define A_STRIDE_B 528            // 264 bf16
#define AH_OFF 0
#define AL_OFF 67584
#define BS_OFF 135168
#define BS_BUF 36864              // 256 * 144
#define FP_OFF 208896
#define FUSED_SMEM 220160

__global__ __launch_bounds__(512, 1) void fused_mma_kernel(
    const float* __restrict__ b3, const float* __restrict__ g0,
    const float* __restrict__ be0, const float* __restrict__ g1,
    const float* __restrict__ be1, float* __restrict__ out)
{
    extern __shared__ char smem[];
    const uint32_t sb = smem_u32(smem);
    float* F   = (float*)(smem + FP_OFF);
    float* h1s = F;          float* b3s = F + 256;
    float* g0s = F + 512;    float* e0s = F + 768;
    float* g1s = F + 1024;   float* e1s = F + 1280;
    float* red_s = F + 1536; float* red_q = F + 2048;   // [128][4]
    float* muS = F + 2560;   float* invS = F + 2688;    // [128]

    const int tid  = threadIdx.x;
    const int lane = tid & 31;
    const int wid  = tid >> 5;
    const int bn   = blockIdx.x;          // 0..511
    const int b    = bn >> 5;
    const int t0   = blockIdx.y * 128;

    // ---- params (threads 0-255) || cp.async chunk 0 (threads 256-511) ----
    if (tid < 256) {
        h1s[tid] = g_h1[(size_t)bn * 256 + tid];
        b3s[tid] = b3[tid];
        g0s[tid] = g0[tid];  e0s[tid] = be0[tid];
        g1s[tid] = g1[tid];  e1s[tid] = be1[tid];
    } else {
        const int t = tid - 256;
#pragma unroll
        for (int i = 0; i < 8; i++) {
            int seg = t + i * 256;          // 0..2047
            int n = seg >> 3, ks = seg & 7;
            CP_ASYNC16(sb + BS_OFF + n * 144 + ks * 16,
                       (const void*)(g_Bhi + n * 256 + ks * 8));
        }
        CP_COMMIT();
    }
    __syncthreads();

    // ---- Phase 1: Hadamard + LN -> Ah/Al rows (threads 0-127) ----
    if (tid < 128) {
        const int r = tid;
        const float4* h2v = (const float4*)(g_h2 + ((size_t)(b * TDIM + t0 + r)) * HH);
        const float4* h1v = (const float4*)h1s;
        float s = 0.f, q = 0.f;
#pragma unroll 8
        for (int j = 0; j < 64; j++) {
            float4 a = h1v[j]; float4 c = h2v[j];
            float p0 = a.x * c.x, p1 = a.y * c.y, p2 = a.z * c.z, p3 = a.w * c.w;
            s += (p0 + p1) + (p2 + p3);
            q += (p0 * p0 + p1 * p1) + (p2 * p2 + p3 * p3);
        }
        const float mu  = s * (1.f / 256.f);
        const float var = q * (1.f / 256.f) - mu * mu;
        const float inv = rsqrtf(var + EPS);
        uint2* ahp = (uint2*)(smem + AH_OFF + r * A_STRIDE_B);
        uint2* alp = (uint2*)(smem + AL_OFF + r * A_STRIDE_B);
#pragma unroll 4
        for (int j = 0; j < 64; j++) {
            float4 a = h1v[j]; float4 c = h2v[j];
            float x0 = (a.x * c.x - mu) * inv * g0s[4 * j + 0] + e0s[4 * j + 0];
            float x1 = (a.y * c.y - mu) * inv * g0s[4 * j + 1] + e0s[4 * j + 1];
            float x2 = (a.z * c.z - mu) * inv * g0s[4 * j + 2] + e0s[4 * j + 2];
            float x3 = (a.w * c.w - mu) * inv * g0s[4 * j + 3] + e0s[4 * j + 3];
            float h0 = __bfloat162float(__float2bfloat16(x0));
            float h1f = __bfloat162float(__float2bfloat16(x1));
            float h2f = __bfloat162float(__float2bfloat16(x2));
            float h3 = __bfloat162float(__float2bfloat16(x3));
            ahp[j] = make_uint2(pack_bf16x2(x0, x1), pack_bf16x2(x2, x3));
            alp[j] = make_uint2(pack_bf16x2(x0 - h0, x1 - h1f),
                                pack_bf16x2(x2 - h2f, x3 - h3));
        }
    }
    __syncthreads();

    // ---- Mainloop ----
    const int wm = wid & 3, wn = wid >> 2;
    const int sub = lane >> 3, r8 = lane & 7;
    const int a_row  = wm * 32 + r8 + (sub & 1) * 8;
    const int a_kadd = (sub >> 1) * 8;
    const int b_nrow = wn * 64 + r8 + (sub >> 1) * 8;
    const int b_kadd = (sub & 1) * 8;

    float c[2][8][4];
#pragma unroll
    for (int mt = 0; mt < 2; mt++)
#pragma unroll
        for (int nt = 0; nt < 8; nt++)
#pragma unroll
            for (int i = 0; i < 4; i++) c[mt][nt][i] = 0.f;

    for (int ch = 0; ch < 12; ch++) {
        CP_WAIT0();
        __syncthreads();
        if (ch < 11) {
            const __nv_bfloat16* src = (ch + 1 >= 8) ? g_Blo : g_Bhi;
            const int kc2 = ((ch + 1) & 3) * 64;
            const uint32_t bsd = sb + BS_OFF + ((ch + 1) & 1) * BS_BUF;
#pragma unroll
            for (int i = 0; i < 4; i++) {
                int seg = tid + i * 512;
                int n = seg >> 3, ks = seg & 7;
                CP_ASYNC16(bsd + n * 144 + ks * 16,
                           (const void*)(src + n * 256 + kc2 + ks * 8));
            }
            CP_COMMIT();
        }
        const uint32_t Abase = sb + (((ch >> 2) == 1) ? AL_OFF : AH_OFF);
        const int kc = (ch & 3) * 64;
        const uint32_t Bbase = sb + BS_OFF + (ch & 1) * BS_BUF;

#pragma unroll
        for (int ks = 0; ks < 4; ks++) {
            uint32_t a[2][4], bq[4][4];
#pragma unroll
            for (int mt = 0; mt < 2; mt++) {
                uint32_t addr = Abase + (uint32_t)((a_row + mt * 16) * A_STRIDE_B
                              + (kc + ks * 16 + a_kadd) * 2);
                LDMX4(a[mt], addr);
            }
#pragma unroll
            for (int nq = 0; nq < 4; nq++) {
                uint32_t addr = Bbase + (uint32_t)((b_nrow + nq * 16) * 144
                              + (ks * 16 + b_kadd) * 2);
                LDMX4(bq[nq], addr);
            }
#pragma unroll
            for (int mt = 0; mt < 2; mt++)
#pragma unroll
                for (int nq = 0; nq < 4; nq++) {
                    MMA16816(c[mt][2 * nq + 0], a[mt], bq[nq][0], bq[nq][1]);
                    MMA16816(c[mt][2 * nq + 1], a[mt], bq[nq][2], bq[nq][3]);
                }
        }
        __syncthreads();
    }

    // ---- Epilogue: +b3, row LN, relu, store ----
    const int rbase = wm * 32 + (lane >> 2);
    const int cbase = wn * 64 + (lane & 3) * 2;

    float s[4], q[4];
#pragma unroll
    for (int mt = 0; mt < 2; mt++)
#pragma unroll
        for (int half = 0; half < 2; half++) {
            float ss = 0.f, qq = 0.f;
#pragma unroll
            for (int nt = 0; nt < 8; nt++) {
                int col = cbase + nt * 8;
                float v0 = c[mt][nt][half * 2 + 0] + b3s[col];
                float v1 = c[mt][nt][half * 2 + 1] + b3s[col + 1];
                c[mt][nt][half * 2 + 0] = v0;
                c[mt][nt][half * 2 + 1] = v1;
                ss += v0 + v1; qq += v0 * v0 + v1 * v1;
            }
            s[mt * 2 + half] = ss; q[mt * 2 + half] = qq;
        }
#pragma unroll
    for (int i = 0; i < 4; i++) {
        s[i] += __shfl_xor_sync(0xffffffffu, s[i], 1);
        s[i] += __shfl_xor_sync(0xffffffffu, s[i], 2);
        q[i] += __shfl_xor_sync(0xffffffffu, q[i], 1);
        q[i] += __shfl_xor_sync(0xffffffffu, q[i], 2);
    }
    if ((lane & 3) == 0) {
#pragma unroll
        for (int mt = 0; mt < 2; mt++)
#pragma unroll
            for (int half = 0; half < 2; half++) {
                int row = rbase + mt * 16 + half * 8;
                red_s[row * 4 + wn] = s[mt * 2 + half];
                red_q[row * 4 + wn] = q[mt * 2 + half];
            }
    }
    __syncthreads();
    if (tid < 128) {
        float ss = red_s[tid * 4] + red_s[tid * 4 + 1] + red_s[tid * 4 + 2] + red_s[tid * 4 + 3];
        float qq = red_q[tid * 4] + red_q[tid * 4 + 1] + red_q[tid * 4 + 2] + red_q[tid * 4 + 3];
        float mu = ss * (1.f / 256.f);
        float var = qq * (1.f / 256.f) - mu * mu;
        muS[tid]  = mu;
        invS[tid] = rsqrtf(var + EPS);
    }
    __syncthreads();

#pragma unroll
    for (int mt = 0; mt < 2; mt++)
#pragma unroll
        for (int half = 0; half < 2; half++) {
            int row = rbase + mt * 16 + half * 8;
            float mu = muS[row], inv = invS[row];
            float2* orow = (float2*)(out + ((size_t)(bn * TDIM + t0 + row)) * HH);
#pragma unroll
            for (int nt = 0; nt < 8; nt++) {
                int col = cbase + nt * 8;
                float o0 = fmaxf((c[mt][nt][half * 2 + 0] - mu) * inv * g1s[col] + e1s[col], 0.f);
                float o1 = fmaxf((c[mt][nt][half * 2 + 1] - mu) * inv * g1s[col + 1] + e1s[col + 1], 0.f);
                orow[col >> 1] = make_float2(o0, o1);
            }
        }
}

// ---------------------------------------------------------------------------
extern "C" void kernel_launch(void* const* d_in, const int* in_sizes, int n_in,
                              void* d_out, int out_size)
{
    const float* x1  = (const float*)d_in[0];
    const float* x2  = (const float*)d_in[1];
    const float* W1  = (const float*)d_in[2];
    const float* b1  = (const float*)d_in[3];
    const float* W2  = (const float*)d_in[4];
    const float* b2  = (const float*)d_in[5];
    const float* W3  = (const float*)d_in[6];
    const float* b3  = (const float*)d_in[7];
    const float* g0  = (const float*)d_in[8];
    const float* be0 = (const float*)d_in[9];
    const float* g1  = (const float*)d_in[10];
    const float* be1 = (const float*)d_in[11];
    float* out = (float*)d_out;

    static int attr_set = 0;
    if (!attr_set) {
        cudaFuncSetAttribute(fused_mma_kernel,
                             cudaFuncAttributeMaxDynamicSharedMemorySize, FUSED_SMEM);
        attr_set = 1;
    }

    prep_w3_kernel<<<256, 256>>>(W3);
    relu_gemm_both<<<144, 256>>>(x1, W1, b1, x2, W2, b2);

    dim3 grid(BB * NN, 2);
    fused_mma_kernel<<<grid, 512, FUSED_SMEM>>>(b3, g0, be0, g1, be1, out);
}

// round 4
// speedup vs baseline: 2.2831x; 1.2517x over previous
#include <cuda_runtime.h>
#include <cuda_bf16.h>
#include <cuda_fp16.h>
#include <cstdint>
#include <math.h>

#define BB   16
#define NN   32
#define TDIM 256
#define HH   256
#define EPS  1e-5f

// ---------------------------------------------------------------------------
// Scratch (__device__ globals; no allocation allowed)
// ---------------------------------------------------------------------------
__device__ float g_h1[BB * NN * HH];                 // [512, 256]
__device__ float g_h2[BB * TDIM * HH];               // [4096, 256]
__device__ __half g_Bh[256 * 256];                   // W3^T fp16 [n][k]

__device__ __forceinline__ uint32_t smem_u32(const void* p) {
    uint32_t a;
    asm("{ .reg .u64 t; cvta.to.shared.u64 t, %1; cvt.u32.u64 %0, t; }" : "=r"(a) : "l"(p));
    return a;
}
__device__ __forceinline__ uint32_t pack_f16x2(float lo, float hi) {
    uint32_t r;
    asm("cvt.rn.f16x2.f32 %0, %1, %2;" : "=r"(r) : "f"(hi), "f"(lo));
    return r;
}

#define LDMX4(r, addr) \
    asm volatile("ldmatrix.sync.aligned.m8n8.x4.shared.b16 {%0,%1,%2,%3}, [%4];" \
        : "=r"((r)[0]), "=r"((r)[1]), "=r"((r)[2]), "=r"((r)[3]) : "r"(addr))

#define MMA16816(cc, a, b0, b1) \
    asm volatile("mma.sync.aligned.m16n8k16.row.col.f32.f16.f16.f32 " \
        "{%0,%1,%2,%3}, {%4,%5,%6,%7}, {%8,%9}, {%0,%1,%2,%3};" \
        : "+f"((cc)[0]), "+f"((cc)[1]), "+f"((cc)[2]), "+f"((cc)[3]) \
        : "r"((a)[0]), "r"((a)[1]), "r"((a)[2]), "r"((a)[3]), "r"(b0), "r"(b1))

#define CP_ASYNC16(dst, src) \
    asm volatile("cp.async.cg.shared.global [%0], [%1], 16;" :: "r"(dst), "l"(src))
#define CP_COMMIT() asm volatile("cp.async.commit_group;" ::: "memory")
#define CP_WAIT0()  asm volatile("cp.async.wait_group 0;" ::: "memory")

// ---------------------------------------------------------------------------
// Prologue: h1 = relu(x1@W1+b1) [blocks 0-15], h2 = relu(x2@W2+b2)
// [blocks 16-143], W3 prep [blocks 144-159]. One launch.
// ---------------------------------------------------------------------------
__global__ __launch_bounds__(256) void prologue_kernel(
    const float* __restrict__ x1, const float* __restrict__ W1, const float* __restrict__ b1,
    const float* __restrict__ x2, const float* __restrict__ W2, const float* __restrict__ b2,
    const float* __restrict__ W3)
{
    if (blockIdx.x >= 144) {
        // W3 [k][n] fp32 -> g_Bh [n][k] fp16
        int base = (blockIdx.x - 144) * 4096 + threadIdx.x * 16;
        int n = base >> 8, k0 = base & 255;
        __half2* dst = (__half2*)(g_Bh + n * 256 + k0);
#pragma unroll
        for (int i = 0; i < 8; i++) {
            float w0 = W3[(k0 + 2 * i) * 256 + n];
            float w1 = W3[(k0 + 2 * i + 1) * 256 + n];
            dst[i] = __floats2half2_rn(w0, w1);
        }
        return;
    }

    const int K = 512;
    __shared__ float Xs[32][32];
    __shared__ float Ws[32 * 256];

    const bool is1 = (blockIdx.x < 16);
    const float* X    = is1 ? x1 : x2;
    const float* W    = is1 ? W1 : W2;
    const float* bias = is1 ? b1 : b2;
    float* O          = is1 ? g_h1 : g_h2;
    const int m0      = (is1 ? blockIdx.x : (blockIdx.x - 16)) * 32;

    const int tid  = threadIdx.x;
    const int lane = tid & 31;
    const int w    = tid >> 5;

    float acc[4][8];
#pragma unroll
    for (int r = 0; r < 4; r++)
#pragma unroll
        for (int c = 0; c < 8; c++) acc[r][c] = 0.f;

    const float4* Wsv = (const float4*)Ws;

    for (int kc = 0; kc < K; kc += 32) {
#pragma unroll
        for (int i = 0; i < 4; i++) {
            int idx = tid + i * 256;
            int r = idx >> 5, k = idx & 31;
            Xs[r][k] = X[(size_t)(m0 + r) * K + kc + k];
        }
        const float4* Wg = (const float4*)(W + (size_t)kc * 256);
        float4* Wv = (float4*)Ws;
#pragma unroll
        for (int i = 0; i < 8; i++) Wv[tid + i * 256] = Wg[tid + i * 256];
        __syncthreads();

#pragma unroll
        for (int k = 0; k < 32; k++) {
            float a[4];
#pragma unroll
            for (int r = 0; r < 4; r++) a[r] = Xs[w + r * 8][k];
            float4 bv0 = Wsv[k * 64 + lane * 2];
            float4 bv1 = Wsv[k * 64 + lane * 2 + 1];
#pragma unroll
            for (int r = 0; r < 4; r++) {
                acc[r][0] = fmaf(a[r], bv0.x, acc[r][0]);
                acc[r][1] = fmaf(a[r], bv0.y, acc[r][1]);
                acc[r][2] = fmaf(a[r], bv0.z, acc[r][2]);
                acc[r][3] = fmaf(a[r], bv0.w, acc[r][3]);
                acc[r][4] = fmaf(a[r], bv1.x, acc[r][4]);
                acc[r][5] = fmaf(a[r], bv1.y, acc[r][5]);
                acc[r][6] = fmaf(a[r], bv1.z, acc[r][6]);
                acc[r][7] = fmaf(a[r], bv1.w, acc[r][7]);
            }
        }
        __syncthreads();
    }

    float bv[8];
#pragma unroll
    for (int c = 0; c < 8; c++) bv[c] = bias[lane * 8 + c];
#pragma unroll
    for (int r = 0; r < 4; r++) {
        int row = m0 + w + r * 8;
        float4 o0, o1;
        o0.x = fmaxf(acc[r][0] + bv[0], 0.f); o0.y = fmaxf(acc[r][1] + bv[1], 0.f);
        o0.z = fmaxf(acc[r][2] + bv[2], 0.f); o0.w = fmaxf(acc[r][3] + bv[3], 0.f);
        o1.x = fmaxf(acc[r][4] + bv[4], 0.f); o1.y = fmaxf(acc[r][5] + bv[5], 0.f);
        o1.z = fmaxf(acc[r][6] + bv[6], 0.f); o1.w = fmaxf(acc[r][7] + bv[7], 0.f);
        float4* op = (float4*)(O + (size_t)row * 256 + lane * 8);
        op[0] = o0; op[1] = o1;
    }
}

// ---------------------------------------------------------------------------
// Fused main kernel (mma.sync fp16, 2-term A-split: (Ah+Al) @ Bh).
// CTA: 128 t-rows x 256 cols, K=256. 512 threads = 16 warps (4m x 4n),
// warp tile 32x64. 4 k-chunks of 64; per chunk both A terms vs same B tile.
// SMEM: Ah[128][264], Al[128][264] fp16; B double buf [256][72] fp16.
// ---------------------------------------------------------------------------
#define A_STRIDE_B 528            // 264 halves
#define AH_OFF 0
#define AL_OFF 67584
#define BS_OFF 135168
#define BS_BUF 36864              // 256 * 144
#define FP_OFF 208896
#define FUSED_SMEM 220160

__global__ __launch_bounds__(512, 1) void fused_mma_kernel(
    const float* __restrict__ b3, const float* __restrict__ g0,
    const float* __restrict__ be0, const float* __restrict__ g1,
    const float* __restrict__ be1, float* __restrict__ out)
{
    extern __shared__ char smem[];
    const uint32_t sb = smem_u32(smem);
    float* F   = (float*)(smem + FP_OFF);
    float* h1s = F;          float* b3s = F + 256;
    float* g0s = F + 512;    float* e0s = F + 768;
    float* g1s = F + 1024;   float* e1s = F + 1280;
    float* red_s = F + 1536; float* red_q = F + 2048;   // [128][4]
    float* muS = F + 2560;   float* invS = F + 2688;    // [128]

    const int tid  = threadIdx.x;
    const int lane = tid & 31;
    const int wid  = tid >> 5;
    const int bn   = blockIdx.x;          // 0..511
    const int b    = bn >> 5;
    const int t0   = blockIdx.y * 128;

    // ---- params (threads 0-255) || cp.async chunk 0 (threads 256-511) ----
    if (tid < 256) {
        h1s[tid] = g_h1[(size_t)bn * 256 + tid];
        b3s[tid] = b3[tid];
        g0s[tid] = g0[tid];  e0s[tid] = be0[tid];
        g1s[tid] = g1[tid];  e1s[tid] = be1[tid];
    } else {
        const int t = tid - 256;
#pragma unroll
        for (int i = 0; i < 8; i++) {
            int seg = t + i * 256;          // 0..2047
            int n = seg >> 3, ks = seg & 7;
            CP_ASYNC16(sb + BS_OFF + n * 144 + ks * 16,
                       (const void*)(g_Bh + n * 256 + ks * 8));
        }
        CP_COMMIT();
    }
    __syncthreads();

    // ---- Phase 1: Hadamard + LN -> Ah/Al rows (threads 0-127) ----
    if (tid < 128) {
        const int r = tid;
        const float4* h2v = (const float4*)(g_h2 + ((size_t)(b * TDIM + t0 + r)) * HH);
        const float4* h1v = (const float4*)h1s;
        float s = 0.f, q = 0.f;
#pragma unroll 8
        for (int j = 0; j < 64; j++) {
            float4 a = h1v[j]; float4 c = h2v[j];
            float p0 = a.x * c.x, p1 = a.y * c.y, p2 = a.z * c.z, p3 = a.w * c.w;
            s += (p0 + p1) + (p2 + p3);
            q += (p0 * p0 + p1 * p1) + (p2 * p2 + p3 * p3);
        }
        const float mu  = s * (1.f / 256.f);
        const float var = q * (1.f / 256.f) - mu * mu;
        const float inv = rsqrtf(var + EPS);
        uint2* ahp = (uint2*)(smem + AH_OFF + r * A_STRIDE_B);
        uint2* alp = (uint2*)(smem + AL_OFF + r * A_STRIDE_B);
#pragma unroll 4
        for (int j = 0; j < 64; j++) {
            float4 a = h1v[j]; float4 c = h2v[j];
            float x0 = (a.x * c.x - mu) * inv * g0s[4 * j + 0] + e0s[4 * j + 0];
            float x1 = (a.y * c.y - mu) * inv * g0s[4 * j + 1] + e0s[4 * j + 1];
            float x2 = (a.z * c.z - mu) * inv * g0s[4 * j + 2] + e0s[4 * j + 2];
            float x3 = (a.w * c.w - mu) * inv * g0s[4 * j + 3] + e0s[4 * j + 3];
            float h0 = __half2float(__float2half_rn(x0));
            float h1f = __half2float(__float2half_rn(x1));
            float h2f = __half2float(__float2half_rn(x2));
            float h3 = __half2float(__float2half_rn(x3));
            ahp[j] = make_uint2(pack_f16x2(x0, x1), pack_f16x2(x2, x3));
            alp[j] = make_uint2(pack_f16x2(x0 - h0, x1 - h1f),
                                pack_f16x2(x2 - h2f, x3 - h3));
        }
    }
    __syncthreads();

    // ---- Mainloop: 4 chunks of K=64, both A terms per chunk ----
    const int wm = wid & 3, wn = wid >> 2;
    const int sub = lane >> 3, r8 = lane & 7;
    const int a_row  = wm * 32 + r8 + (sub & 1) * 8;
    const int a_kadd = (sub >> 1) * 8;
    const int b_nrow = wn * 64 + r8 + (sub >> 1) * 8;
    const int b_kadd = (sub & 1) * 8;

    float c[2][8][4];
#pragma unroll
    for (int mt = 0; mt < 2; mt++)
#pragma unroll
        for (int nt = 0; nt < 8; nt++)
#pragma unroll
            for (int i = 0; i < 4; i++) c[mt][nt][i] = 0.f;

    for (int ch = 0; ch < 4; ch++) {
        CP_WAIT0();
        __syncthreads();
        if (ch < 3) {
            const int kc2 = (ch + 1) * 64;
            const uint32_t bsd = sb + BS_OFF + ((ch + 1) & 1) * BS_BUF;
#pragma unroll
            for (int i = 0; i < 4; i++) {
                int seg = tid + i * 512;
                int n = seg >> 3, ks = seg & 7;
                CP_ASYNC16(bsd + n * 144 + ks * 16,
                           (const void*)(g_Bh + n * 256 + kc2 + ks * 8));
            }
            CP_COMMIT();
        }
        const int kc = ch * 64;
        const uint32_t Bbase = sb + BS_OFF + (ch & 1) * BS_BUF;

#pragma unroll
        for (int ks = 0; ks < 4; ks++) {
            uint32_t bq[4][4], a[2][4];
#pragma unroll
            for (int nq = 0; nq < 4; nq++) {
                uint32_t addr = Bbase + (uint32_t)((b_nrow + nq * 16) * 144
                              + (ks * 16 + b_kadd) * 2);
                LDMX4(bq[nq], addr);
            }
            const uint32_t a_off = (uint32_t)(a_row * A_STRIDE_B
                                 + (kc + ks * 16 + a_kadd) * 2);
            // term 1: Ah
#pragma unroll
            for (int mt = 0; mt < 2; mt++)
                LDMX4(a[mt], sb + AH_OFF + a_off + mt * 16 * A_STRIDE_B);
#pragma unroll
            for (int mt = 0; mt < 2; mt++)
#pragma unroll
                for (int nq = 0; nq < 4; nq++) {
                    MMA16816(c[mt][2 * nq + 0], a[mt], bq[nq][0], bq[nq][1]);
                    MMA16816(c[mt][2 * nq + 1], a[mt], bq[nq][2], bq[nq][3]);
                }
            // term 2: Al (same B frags)
#pragma unroll
            for (int mt = 0; mt < 2; mt++)
                LDMX4(a[mt], sb + AL_OFF + a_off + mt * 16 * A_STRIDE_B);
#pragma unroll
            for (int mt = 0; mt < 2; mt++)
#pragma unroll
                for (int nq = 0; nq < 4; nq++) {
                    MMA16816(c[mt][2 * nq + 0], a[mt], bq[nq][0], bq[nq][1]);
                    MMA16816(c[mt][2 * nq + 1], a[mt], bq[nq][2], bq[nq][3]);
                }
        }
        __syncthreads();
    }

    // ---- Epilogue: +b3, row LN, relu, store ----
    const int rbase = wm * 32 + (lane >> 2);
    const int cbase = wn * 64 + (lane & 3) * 2;

    float s[4], q[4];
#pragma unroll
    for (int mt = 0; mt < 2; mt++)
#pragma unroll
        for (int half = 0; half < 2; half++) {
            float ss = 0.f, qq = 0.f;
#pragma unroll
            for (int nt = 0; nt < 8; nt++) {
                int col = cbase + nt * 8;
                float v0 = c[mt][nt][half * 2 + 0] + b3s[col];
                float v1 = c[mt][nt][half * 2 + 1] + b3s[col + 1];
                c[mt][nt][half * 2 + 0] = v0;
                c[mt][nt][half * 2 + 1] = v1;
                ss += v0 + v1; qq += v0 * v0 + v1 * v1;
            }
            s[mt * 2 + half] = ss; q[mt * 2 + half] = qq;
        }
#pragma unroll
    for (int i = 0; i < 4; i++) {
        s[i] += __shfl_xor_sync(0xffffffffu, s[i], 1);
        s[i] += __shfl_xor_sync(0xffffffffu, s[i], 2);
        q[i] += __shfl_xor_sync(0xffffffffu, q[i], 1);
        q[i] += __shfl_xor_sync(0xffffffffu, q[i], 2);
    }
    if ((lane & 3) == 0) {
#pragma unroll
        for (int mt = 0; mt < 2; mt++)
#pragma unroll
            for (int half = 0; half < 2; half++) {
                int row = rbase + mt * 16 + half * 8;
                red_s[row * 4 + wn] = s[mt * 2 + half];
                red_q[row * 4 + wn] = q[mt * 2 + half];
            }
    }
    __syncthreads();
    if (tid < 128) {
        float ss = red_s[tid * 4] + red_s[tid * 4 + 1] + red_s[tid * 4 + 2] + red_s[tid * 4 + 3];
        float qq = red_q[tid * 4] + red_q[tid * 4 + 1] + red_q[tid * 4 + 2] + red_q[tid * 4 + 3];
        float mu = ss * (1.f / 256.f);
        float var = qq * (1.f / 256.f) - mu * mu;
        muS[tid]  = mu;
        invS[tid] = rsqrtf(var + EPS);
    }
    __syncthreads();

#pragma unroll
    for (int mt = 0; mt < 2; mt++)
#pragma unroll
        for (int half = 0; half < 2; half++) {
            int row = rbase + mt * 16 + half * 8;
            float mu = muS[row], inv = invS[row];
            float2* orow = (float2*)(out + ((size_t)(bn * TDIM + t0 + row)) * HH);
#pragma unroll
            for (int nt = 0; nt < 8; nt++) {
                int col = cbase + nt * 8;
                float o0 = fmaxf((c[mt][nt][half * 2 + 0] - mu) * inv * g1s[col] + e1s[col], 0.f);
                float o1 = fmaxf((c[mt][nt][half * 2 + 1] - mu) * inv * g1s[col + 1] + e1s[col + 1], 0.f);
                orow[col >> 1] = make_float2(o0, o1);
            }
        }
}

// ---------------------------------------------------------------------------
extern "C" void kernel_launch(void* const* d_in, const int* in_sizes, int n_in,
                              void* d_out, int out_size)
{
    const float* x1  = (const float*)d_in[0];
    const float* x2  = (const float*)d_in[1];
    const float* W1  = (const float*)d_in[2];
    const float* b1  = (const float*)d_in[3];
    const float* W2  = (const float*)d_in[4];
    const float* b2  = (const float*)d_in[5];
    const float* W3  = (const float*)d_in[6];
    const float* b3  = (const float*)d_in[7];
    const float* g0  = (const float*)d_in[8];
    const float* be0 = (const float*)d_in[9];
    const float* g1  = (const float*)d_in[10];
    const float* be1 = (const float*)d_in[11];
    float* out = (float*)d_out;

    static int attr_set = 0;
    if (!attr_set) {
        cudaFuncSetAttribute(fused_mma_kernel,
                             cudaFuncAttributeMaxDynamicSharedMemorySize, FUSED_SMEM);
        attr_set = 1;
    }

    prologue_kernel<<<160, 256>>>(x1, W1, b1, x2, W2, b2, W3);

    dim3 grid(BB * NN, 2);
    fused_mma_kernel<<<grid, 512, FUSED_SMEM>>>(b3, g0, be0, g1, be1, out);
}

// round 5
// speedup vs baseline: 2.3425x; 1.0260x over previous
#include <cuda_runtime.h>
#include <cuda_bf16.h>
#include <cuda_fp16.h>
#include <cstdint>
#include <math.h>

#define BB   16
#define NN   32
#define TDIM 256
#define HH   256
#define EPS  1e-5f

// ---------------------------------------------------------------------------
// Scratch (__device__ globals; no allocation allowed)
// ---------------------------------------------------------------------------
__device__ float g_h1[BB * NN * HH];                 // [512, 256]
__device__ float g_h2[BB * TDIM * HH];               // [4096, 256]
__device__ __half g_Bh[256 * 256];                   // W3^T fp16 [n][k]

__device__ __forceinline__ uint32_t smem_u32(const void* p) {
    uint32_t a;
    asm("{ .reg .u64 t; cvta.to.shared.u64 t, %1; cvt.u32.u64 %0, t; }" : "=r"(a) : "l"(p));
    return a;
}
__device__ __forceinline__ uint32_t pack_f16x2(float lo, float hi) {
    uint32_t r;
    asm("cvt.rn.f16x2.f32 %0, %1, %2;" : "=r"(r) : "f"(hi), "f"(lo));
    return r;
}

#define LDMX4(r, addr) \
    asm volatile("ldmatrix.sync.aligned.m8n8.x4.shared.b16 {%0,%1,%2,%3}, [%4];" \
        : "=r"((r)[0]), "=r"((r)[1]), "=r"((r)[2]), "=r"((r)[3]) : "r"(addr))

#define MMA16816(cc, a, b0, b1) \
    asm volatile("mma.sync.aligned.m16n8k16.row.col.f32.f16.f16.f32 " \
        "{%0,%1,%2,%3}, {%4,%5,%6,%7}, {%8,%9}, {%0,%1,%2,%3};" \
        : "+f"((cc)[0]), "+f"((cc)[1]), "+f"((cc)[2]), "+f"((cc)[3]) \
        : "r"((a)[0]), "r"((a)[1]), "r"((a)[2]), "r"((a)[3]), "r"(b0), "r"(b1))

#define CP_ASYNC16(dst, src) \
    asm volatile("cp.async.cg.shared.global [%0], [%1], 16;" :: "r"(dst), "l"(src))
#define CP_COMMIT() asm volatile("cp.async.commit_group;" ::: "memory")
#define CP_WAIT0()  asm volatile("cp.async.wait_group 0;" ::: "memory")

// ---------------------------------------------------------------------------
// Prologue: h1 = relu(x1@W1+b1) [blocks 0-15], h2 = relu(x2@W2+b2)
// [blocks 16-143], W3 prep [blocks 144-159]. One launch.
// ---------------------------------------------------------------------------
__global__ __launch_bounds__(256) void prologue_kernel(
    const float* __restrict__ x1, const float* __restrict__ W1, const float* __restrict__ b1,
    const float* __restrict__ x2, const float* __restrict__ W2, const float* __restrict__ b2,
    const float* __restrict__ W3)
{
    if (blockIdx.x >= 144) {
        int base = (blockIdx.x - 144) * 4096 + threadIdx.x * 16;
        int n = base >> 8, k0 = base & 255;
        __half2* dst = (__half2*)(g_Bh + n * 256 + k0);
#pragma unroll
        for (int i = 0; i < 8; i++) {
            float w0 = W3[(k0 + 2 * i) * 256 + n];
            float w1 = W3[(k0 + 2 * i + 1) * 256 + n];
            dst[i] = __floats2half2_rn(w0, w1);
        }
        return;
    }

    const int K = 512;
    __shared__ float Xs[32][32];
    __shared__ float Ws[32 * 256];

    const bool is1 = (blockIdx.x < 16);
    const float* X    = is1 ? x1 : x2;
    const float* W    = is1 ? W1 : W2;
    const float* bias = is1 ? b1 : b2;
    float* O          = is1 ? g_h1 : g_h2;
    const int m0      = (is1 ? blockIdx.x : (blockIdx.x - 16)) * 32;

    const int tid  = threadIdx.x;
    const int lane = tid & 31;
    const int w    = tid >> 5;

    float acc[4][8];
#pragma unroll
    for (int r = 0; r < 4; r++)
#pragma unroll
        for (int c = 0; c < 8; c++) acc[r][c] = 0.f;

    const float4* Wsv = (const float4*)Ws;

    for (int kc = 0; kc < K; kc += 32) {
#pragma unroll
        for (int i = 0; i < 4; i++) {
            int idx = tid + i * 256;
            int r = idx >> 5, k = idx & 31;
            Xs[r][k] = X[(size_t)(m0 + r) * K + kc + k];
        }
        const float4* Wg = (const float4*)(W + (size_t)kc * 256);
        float4* Wv = (float4*)Ws;
#pragma unroll
        for (int i = 0; i < 8; i++) Wv[tid + i * 256] = Wg[tid + i * 256];
        __syncthreads();

#pragma unroll
        for (int k = 0; k < 32; k++) {
            float a[4];
#pragma unroll
            for (int r = 0; r < 4; r++) a[r] = Xs[w + r * 8][k];
            float4 bv0 = Wsv[k * 64 + lane * 2];
            float4 bv1 = Wsv[k * 64 + lane * 2 + 1];
#pragma unroll
            for (int r = 0; r < 4; r++) {
                acc[r][0] = fmaf(a[r], bv0.x, acc[r][0]);
                acc[r][1] = fmaf(a[r], bv0.y, acc[r][1]);
                acc[r][2] = fmaf(a[r], bv0.z, acc[r][2]);
                acc[r][3] = fmaf(a[r], bv0.w, acc[r][3]);
                acc[r][4] = fmaf(a[r], bv1.x, acc[r][4]);
                acc[r][5] = fmaf(a[r], bv1.y, acc[r][5]);
                acc[r][6] = fmaf(a[r], bv1.z, acc[r][6]);
                acc[r][7] = fmaf(a[r], bv1.w, acc[r][7]);
            }
        }
        __syncthreads();
    }

    float bv[8];
#pragma unroll
    for (int c = 0; c < 8; c++) bv[c] = bias[lane * 8 + c];
#pragma unroll
    for (int r = 0; r < 4; r++) {
        int row = m0 + w + r * 8;
        float4 o0, o1;
        o0.x = fmaxf(acc[r][0] + bv[0], 0.f); o0.y = fmaxf(acc[r][1] + bv[1], 0.f);
        o0.z = fmaxf(acc[r][2] + bv[2], 0.f); o0.w = fmaxf(acc[r][3] + bv[3], 0.f);
        o1.x = fmaxf(acc[r][4] + bv[4], 0.f); o1.y = fmaxf(acc[r][5] + bv[5], 0.f);
        o1.z = fmaxf(acc[r][6] + bv[6], 0.f); o1.w = fmaxf(acc[r][7] + bv[7], 0.f);
        float4* op = (float4*)(O + (size_t)row * 256 + lane * 8);
        op[0] = o0; op[1] = o1;
    }
}

// ---------------------------------------------------------------------------
// Fused main kernel: single fp16 term, 1024 threads = 32 warps (4m x 8n),
// warp tile 32x32. CTA tile 128 x 256, K=256, 4 chunks of 64.
// SMEM: A 128x512B XOR-swizzled (64KB); B double-buffer 2x32KB swizzled.
// ---------------------------------------------------------------------------
#define A_OFF 0
#define B_OFF 65536
#define B_BUF 32768
#define FP_OFF 131072
#define FUSED_SMEM 146432

__global__ __launch_bounds__(1024, 1) void fused_mma_kernel(
    const float* __restrict__ b3, const float* __restrict__ g0,
    const float* __restrict__ be0, const float* __restrict__ g1,
    const float* __restrict__ be1, float* __restrict__ out)
{
    extern __shared__ char smem[];
    const uint32_t sb = smem_u32(smem);
    float* F   = (float*)(smem + FP_OFF);
    float* h1s = F;          float* b3s = F + 256;
    float* g0s = F + 512;    float* e0s = F + 768;
    float* g1s = F + 1024;   float* e1s = F + 1280;
    float* red_s = F + 1536;   // [128][8]
    float* red_q = F + 2560;   // [128][8]
    float* muS   = F + 3584;   // [128]
    float* invS  = F + 3712;   // [128]

    const int tid  = threadIdx.x;
    const int lane = tid & 31;
    const int wid  = tid >> 5;          // 0..31
    const int bn   = blockIdx.x;        // 0..511
    const int b    = bn >> 5;
    const int t0   = blockIdx.y * 128;

    // ---- B chunk 0 cp.async (all threads, 2 x 16B each) ----
#pragma unroll
    for (int i = 0; i < 2; i++) {
        int seg = tid + i * 1024;       // 0..2047
        int n = seg >> 3, u = seg & 7;
        uint32_t dst = sb + B_OFF + n * 128 + ((u * 16) ^ ((n & 7) * 16));
        CP_ASYNC16(dst, (const void*)(g_Bh + n * 256 + u * 8));
    }
    CP_COMMIT();

    if (tid < 256) {
        h1s[tid] = g_h1[(size_t)bn * 256 + tid];
        b3s[tid] = b3[tid];
        g0s[tid] = g0[tid];  e0s[tid] = be0[tid];
        g1s[tid] = g1[tid];  e1s[tid] = be1[tid];
    }
    __syncthreads();

    // ---- Phase 1: Hadamard + LN -> A fp16 swizzled. Warp w: rows w,w+32,w+64,w+96.
    // Lane owns cols [lane*8, lane*8+8).
#pragma unroll
    for (int rr = 0; rr < 4; rr++) {
        const int r = wid + rr * 32;
        const float4* h2v = (const float4*)(g_h2 + ((size_t)(b * TDIM + t0 + r)) * HH) + lane * 2;
        const float4* h1v = (const float4*)h1s + lane * 2;
        float4 a0 = h1v[0], a1 = h1v[1];
        float4 c0 = h2v[0], c1 = h2v[1];
        float p[8];
        p[0] = a0.x * c0.x; p[1] = a0.y * c0.y; p[2] = a0.z * c0.z; p[3] = a0.w * c0.w;
        p[4] = a1.x * c1.x; p[5] = a1.y * c1.y; p[6] = a1.z * c1.z; p[7] = a1.w * c1.w;
        float s = 0.f, q = 0.f;
#pragma unroll
        for (int j = 0; j < 8; j++) { s += p[j]; q += p[j] * p[j]; }
#pragma unroll
        for (int o = 16; o > 0; o >>= 1) {
            s += __shfl_xor_sync(0xffffffffu, s, o);
            q += __shfl_xor_sync(0xffffffffu, q, o);
        }
        const float mu  = s * (1.f / 256.f);
        const float var = q * (1.f / 256.f) - mu * mu;
        const float inv = rsqrtf(var + EPS);
        float x[8];
#pragma unroll
        for (int j = 0; j < 8; j++)
            x[j] = (p[j] - mu) * inv * g0s[lane * 8 + j] + e0s[lane * 8 + j];
        uint4 wv;
        wv.x = pack_f16x2(x[0], x[1]); wv.y = pack_f16x2(x[2], x[3]);
        wv.z = pack_f16x2(x[4], x[5]); wv.w = pack_f16x2(x[6], x[7]);
        uint32_t unit = ((uint32_t)(lane * 16)) ^ ((uint32_t)(r & 7) * 16u);
        *(uint4*)(smem + A_OFF + r * 512 + unit) = wv;
    }
    __syncthreads();

    // ---- Mainloop ----
    const int wm = wid & 3, wn = wid >> 2;       // wm 0..3, wn 0..7
    const int sub = lane >> 3, r8 = lane & 7;
    const int a_row = wm * 32 + r8 + (sub & 1) * 8;
    const int a_kb  = (sub >> 1) * 16;           // byte offset (0 or 16)
    const int b_nrow = wn * 32 + r8 + (sub >> 1) * 8;
    const int b_kb  = (sub & 1) * 16;

    float c[2][4][4];
#pragma unroll
    for (int mt = 0; mt < 2; mt++)
#pragma unroll
        for (int nt = 0; nt < 4; nt++)
#pragma unroll
            for (int i = 0; i < 4; i++) c[mt][nt][i] = 0.f;

    for (int ch = 0; ch < 4; ch++) {
        CP_WAIT0();
        __syncthreads();
        if (ch < 3) {
            const int kc2 = (ch + 1) * 64;
            const uint32_t bsd = sb + B_OFF + ((ch + 1) & 1) * B_BUF;
#pragma unroll
            for (int i = 0; i < 2; i++) {
                int seg = tid + i * 1024;
                int n = seg >> 3, u = seg & 7;
                uint32_t dst = bsd + n * 128 + ((u * 16) ^ ((n & 7) * 16));
                CP_ASYNC16(dst, (const void*)(g_Bh + n * 256 + kc2 + u * 8));
            }
            CP_COMMIT();
        }
        const int kcb = ch * 128;                 // byte offset of chunk in A row
        const uint32_t Bb = sb + B_OFF + (ch & 1) * B_BUF;

#pragma unroll
        for (int ks = 0; ks < 4; ks++) {
            uint32_t bq[2][4], a[2][4];
            const int kbyte = ks * 32;
#pragma unroll
            for (int nq = 0; nq < 2; nq++) {
                const int nrow = b_nrow + nq * 16;
                uint32_t addr = Bb + nrow * 128
                              + (uint32_t)((kbyte + b_kb) ^ ((nrow & 7) * 16));
                LDMX4(bq[nq], addr);
            }
#pragma unroll
            for (int mt = 0; mt < 2; mt++) {
                const int arow = a_row + mt * 16;
                uint32_t addr = sb + A_OFF + arow * 512
                              + (uint32_t)((kcb + kbyte + a_kb) ^ ((arow & 7) * 16));
                LDMX4(a[mt], addr);
            }
#pragma unroll
            for (int mt = 0; mt < 2; mt++)
#pragma unroll
                for (int nq = 0; nq < 2; nq++) {
                    MMA16816(c[mt][2 * nq + 0], a[mt], bq[nq][0], bq[nq][1]);
                    MMA16816(c[mt][2 * nq + 1], a[mt], bq[nq][2], bq[nq][3]);
                }
        }
    }
    __syncthreads();

    // ---- Epilogue: +b3, row LN, relu, store ----
    const int rbase = wm * 32 + (lane >> 2);
    const int cbase = wn * 32 + (lane & 3) * 2;

    float s[4], q[4];
#pragma unroll
    for (int mt = 0; mt < 2; mt++)
#pragma unroll
        for (int half = 0; half < 2; half++) {
            float ss = 0.f, qq = 0.f;
#pragma unroll
            for (int nt = 0; nt < 4; nt++) {
                int col = cbase + nt * 8;
                float v0 = c[mt][nt][half * 2 + 0] + b3s[col];
                float v1 = c[mt][nt][half * 2 + 1] + b3s[col + 1];
                c[mt][nt][half * 2 + 0] = v0;
                c[mt][nt][half * 2 + 1] = v1;
                ss += v0 + v1; qq += v0 * v0 + v1 * v1;
            }
            s[mt * 2 + half] = ss; q[mt * 2 + half] = qq;
        }
#pragma unroll
    for (int i = 0; i < 4; i++) {
        s[i] += __shfl_xor_sync(0xffffffffu, s[i], 1);
        s[i] += __shfl_xor_sync(0xffffffffu, s[i], 2);
        q[i] += __shfl_xor_sync(0xffffffffu, q[i], 1);
        q[i] += __shfl_xor_sync(0xffffffffu, q[i], 2);
    }
    if ((lane & 3) == 0) {
#pragma unroll
        for (int mt = 0; mt < 2; mt++)
#pragma unroll
            for (int half = 0; half < 2; half++) {
                int row = rbase + mt * 16 + half * 8;
                red_s[row * 8 + wn] = s[mt * 2 + half];
                red_q[row * 8 + wn] = q[mt * 2 + half];
            }
    }
    __syncthreads();
    if (tid < 128) {
        float ss = 0.f, qq = 0.f;
#pragma unroll
        for (int i = 0; i < 8; i++) { ss += red_s[tid * 8 + i]; qq += red_q[tid * 8 + i]; }
        float mu = ss * (1.f / 256.f);
        float var = qq * (1.f / 256.f) - mu * mu;
        muS[tid]  = mu;
        invS[tid] = rsqrtf(var + EPS);
    }
    __syncthreads();

#pragma unroll
    for (int mt = 0; mt < 2; mt++)
#pragma unroll
        for (int half = 0; half < 2; half++) {
            int row = rbase + mt * 16 + half * 8;
            float mu = muS[row], inv = invS[row];
            float2* orow = (float2*)(out + ((size_t)(bn * TDIM + t0 + row)) * HH);
#pragma unroll
            for (int nt = 0; nt < 4; nt++) {
                int col = cbase + nt * 8;
                float o0 = fmaxf((c[mt][nt][half * 2 + 0] - mu) * inv * g1s[col] + e1s[col], 0.f);
                float o1 = fmaxf((c[mt][nt][half * 2 + 1] - mu) * inv * g1s[col + 1] + e1s[col + 1], 0.f);
                orow[col >> 1] = make_float2(o0, o1);
            }
        }
}

// ---------------------------------------------------------------------------
extern "C" void kernel_launch(void* const* d_in, const int* in_sizes, int n_in,
                              void* d_out, int out_size)
{
    const float* x1  = (const float*)d_in[0];
    const float* x2  = (const float*)d_in[1];
    const float* W1  = (const float*)d_in[2];
    const float* b1  = (const float*)d_in[3];
    const float* W2  = (const float*)d_in[4];
    const float* b2  = (const float*)d_in[5];
    const float* W3  = (const float*)d_in[6];
    const float* b3  = (const float*)d_in[7];
    const float* g0  = (const float*)d_in[8];
    const float* be0 = (const float*)d_in[9];
    const float* g1  = (const float*)d_in[10];
    const float* be1 = (const float*)d_in[11];
    float* out = (float*)d_out;

    static int attr_set = 0;
    if (!attr_set) {
        cudaFuncSetAttribute(fused_mma_kernel,
                             cudaFuncAttributeMaxDynamicSharedMemorySize, FUSED_SMEM);
        attr_set = 1;
    }

    prologue_kernel<<<160, 256>>>(x1, W1, b1, x2, W2, b2, W3);

    dim3 grid(BB * NN, 2);
    fused_mma_kernel<<<grid, 1024, FUSED_SMEM>>>(b3, g0, be0, g1, be1, out);
}

// round 6
// speedup vs baseline: 4.8328x; 2.0631x over previous
#include <cuda_runtime.h>
#include <cuda_bf16.h>
#include <cuda_fp16.h>
#include <cstdint>
#include <math.h>

#define BB   16
#define NN   32
#define TDIM 256
#define HH   256
#define EPS  1e-5f

// ---------------------------------------------------------------------------
// Scratch (__device__ globals; no allocation allowed)
// ---------------------------------------------------------------------------
__device__ float g_h1[BB * NN * HH];                 // [512, 256]
__device__ float g_h2[BB * TDIM * HH];               // [4096, 256]
__device__ __half g_Bh[256 * 256];                   // W3^T fp16 [n][k]
__device__ __half g_W1h[256 * 512];                  // W1^T hi [n][k]
__device__ __half g_W1l[256 * 512];                  // W1^T lo
__device__ __half g_W2h[256 * 512];                  // W2^T hi
__device__ __half g_W2l[256 * 512];                  // W2^T lo

__device__ __forceinline__ uint32_t smem_u32(const void* p) {
    uint32_t a;
    asm("{ .reg .u64 t; cvta.to.shared.u64 t, %1; cvt.u32.u64 %0, t; }" : "=r"(a) : "l"(p));
    return a;
}
__device__ __forceinline__ uint32_t pack_f16x2(float lo, float hi) {
    uint32_t r;
    asm("cvt.rn.f16x2.f32 %0, %1, %2;" : "=r"(r) : "f"(hi), "f"(lo));
    return r;
}

#define LDMX4(r, addr) \
    asm volatile("ldmatrix.sync.aligned.m8n8.x4.shared.b16 {%0,%1,%2,%3}, [%4];" \
        : "=r"((r)[0]), "=r"((r)[1]), "=r"((r)[2]), "=r"((r)[3]) : "r"(addr))

#define MMA16816(cc, a, b0, b1) \
    asm volatile("mma.sync.aligned.m16n8k16.row.col.f32.f16.f16.f32 " \
        "{%0,%1,%2,%3}, {%4,%5,%6,%7}, {%8,%9}, {%0,%1,%2,%3};" \
        : "+f"((cc)[0]), "+f"((cc)[1]), "+f"((cc)[2]), "+f"((cc)[3]) \
        : "r"((a)[0]), "r"((a)[1]), "r"((a)[2]), "r"((a)[3]), "r"(b0), "r"(b1))

#define CP_ASYNC16(dst, src) \
    asm volatile("cp.async.cg.shared.global [%0], [%1], 16;" :: "r"(dst), "l"(src))
#define CP_COMMIT() asm volatile("cp.async.commit_group;" ::: "memory")
#define CP_WAIT0()  asm volatile("cp.async.wait_group 0;" ::: "memory")

// ---------------------------------------------------------------------------
// Prep: transpose + fp16(hi/lo) conversion of W1, W2; fp16 transpose of W3.
// Blocks 0-127: W1; 128-255: W2; 256-319: W3. 256 threads, 32x32 tiles.
// ---------------------------------------------------------------------------
__global__ __launch_bounds__(256) void prep_kernel(
    const float* __restrict__ W1, const float* __restrict__ W2,
    const float* __restrict__ W3)
{
    __shared__ float t[32][33];
    const int bid = blockIdx.x;
    const int tid = threadIdx.x;
    const float* W;
    __half *Oh, *Ol;
    int idx, KK;
    if (bid < 128)      { W = W1; Oh = g_W1h; Ol = g_W1l; idx = bid;       KK = 512; }
    else if (bid < 256) { W = W2; Oh = g_W2h; Ol = g_W2l; idx = bid - 128; KK = 512; }
    else                { W = W3; Oh = g_Bh;  Ol = nullptr; idx = bid - 256; KK = 256; }

    const int tile_k = idx >> 3, tile_n = idx & 7;
    const int tx = tid & 31, ty = tid >> 5;

#pragma unroll
    for (int i = 0; i < 4; i++)
        t[ty + i * 8][tx] = W[(size_t)(tile_k * 32 + ty + i * 8) * 256 + tile_n * 32 + tx];
    __syncthreads();

#pragma unroll
    for (int i = 0; i < 4; i++) {
        const int nl = ty + i * 8, kl = tx;
        float v = t[kl][nl];
        __half h = __float2half_rn(v);
        size_t o = (size_t)(tile_n * 32 + nl) * KK + tile_k * 32 + kl;
        Oh[o] = h;
        if (Ol) Ol[o] = __float2half_rn(v - __half2float(h));
    }
}

// ---------------------------------------------------------------------------
// tc_prologue: h = relu(X @ W + b) with fp16 3-term split.
// Blocks 0-15: h1 (x1, 512 rows). Blocks 16-143: h2 (x2, 4096 rows).
// CTA tile 32 rows x 256 cols, K=512 (8 chunks of 64). 512 threads, 16 warps
// (2m x 8n), warp tile 16x32. A (X hi/lo) converted to smem up-front;
// B (W^T hi/lo) double-buffered cp.async.
// ---------------------------------------------------------------------------
#define PAH 0
#define PAL 32768
#define PBH 65536
#define PBL 131072
#define PBIAS 196608
#define PROLOGUE_SMEM 197664

__global__ __launch_bounds__(512, 1) void tc_prologue(
    const float* __restrict__ x1, const float* __restrict__ b1,
    const float* __restrict__ x2, const float* __restrict__ b2)
{
    extern __shared__ char smem[];
    const uint32_t sb = smem_u32(smem);
    float* bs = (float*)(smem + PBIAS);

    const bool is1 = (blockIdx.x < 16);
    const float* X    = is1 ? x1 : x2;
    const __half* Wh  = is1 ? g_W1h : g_W2h;
    const __half* Wl  = is1 ? g_W1l : g_W2l;
    const float* bias = is1 ? b1 : b2;
    float* O          = is1 ? g_h1 : g_h2;
    const int m0      = (is1 ? blockIdx.x : (blockIdx.x - 16)) * 32;

    const int tid  = threadIdx.x;
    const int lane = tid & 31;
    const int wid  = tid >> 5;

    // ---- chunk 0 cp.async (Bh then Bl) ----
#pragma unroll
    for (int i = 0; i < 8; i++) {
        int seg = tid + i * 512;                  // 0..4095
        int n = (seg & 2047) >> 3, u = seg & 7;
        uint32_t base = (seg < 2048) ? (sb + PBH) : (sb + PBL);
        const __half* src = (seg < 2048) ? Wh : Wl;
        CP_ASYNC16(base + n * 128 + ((u * 16) ^ ((n & 7) * 16)),
                   (const void*)(src + n * 512 + u * 8));
    }
    CP_COMMIT();

    if (tid < 256) bs[tid] = bias[tid];

    // ---- A: load X rows fp32, split hi/lo fp16 into smem (swizzled) ----
    {
        const int arow = tid >> 4;                // 0..31
        const int k0   = (tid & 15) * 32;         // 0..480
        const float4* xp = (const float4*)(X + (size_t)(m0 + arow) * 512 + k0);
        uint32_t hiu[16], lou[16];
#pragma unroll
        for (int j = 0; j < 8; j++) {
            float4 v = xp[j];
            float h0 = __half2float(__float2half_rn(v.x));
            float h1f = __half2float(__float2half_rn(v.y));
            float h2f = __half2float(__float2half_rn(v.z));
            float h3 = __half2float(__float2half_rn(v.w));
            hiu[2 * j]     = pack_f16x2(v.x, v.y);
            hiu[2 * j + 1] = pack_f16x2(v.z, v.w);
            lou[2 * j]     = pack_f16x2(v.x - h0, v.y - h1f);
            lou[2 * j + 1] = pack_f16x2(v.z - h2f, v.w - h3);
        }
        const uint32_t rbase = arow * 1024;
        const uint32_t rsw   = (uint32_t)(arow & 7) * 16u;
#pragma unroll
        for (int jj = 0; jj < 4; jj++) {
            uint32_t kbyte = (uint32_t)(k0 * 2 + jj * 16);
            uint32_t off = rbase + (kbyte ^ rsw);
            *(uint4*)(smem + PAH + off) = make_uint4(hiu[4*jj], hiu[4*jj+1], hiu[4*jj+2], hiu[4*jj+3]);
            *(uint4*)(smem + PAL + off) = make_uint4(lou[4*jj], lou[4*jj+1], lou[4*jj+2], lou[4*jj+3]);
        }
    }
    __syncthreads();

    // ---- mainloop ----
    const int wm = wid & 1, wn = wid >> 1;        // 2m x 8n
    const int sub = lane >> 3, r8 = lane & 7;
    const int a_row = wm * 16 + r8 + (sub & 1) * 8;
    const int a_kb  = (sub >> 1) * 16;
    const int b_nrow = wn * 32 + r8 + (sub >> 1) * 8;
    const int b_kb  = (sub & 1) * 16;

    float c[4][4];
#pragma unroll
    for (int nt = 0; nt < 4; nt++)
#pragma unroll
        for (int i = 0; i < 4; i++) c[nt][i] = 0.f;

    for (int ch = 0; ch < 8; ch++) {
        CP_WAIT0();
        __syncthreads();
        if (ch < 7) {
            const int kc2 = (ch + 1) * 64;
            const uint32_t buf = ((ch + 1) & 1) * 32768u;
#pragma unroll
            for (int i = 0; i < 8; i++) {
                int seg = tid + i * 512;
                int n = (seg & 2047) >> 3, u = seg & 7;
                uint32_t base = (seg < 2048) ? (sb + PBH + buf) : (sb + PBL + buf);
                const __half* src = (seg < 2048) ? Wh : Wl;
                CP_ASYNC16(base + n * 128 + ((u * 16) ^ ((n & 7) * 16)),
                           (const void*)(src + n * 512 + kc2 + u * 8));
            }
            CP_COMMIT();
        }
        const uint32_t buf = (ch & 1) * 32768u;
        const uint32_t Bh = sb + PBH + buf;
        const uint32_t Bl = sb + PBL + buf;
        const int kcb = ch * 128;

#pragma unroll
        for (int ks = 0; ks < 4; ks++) {
            const int kbyte = ks * 32;
            uint32_t ah[4], al[4], bh[2][4], bl[2][4];
            {
                uint32_t off = a_row * 1024 + (uint32_t)((kcb + kbyte + a_kb) ^ ((a_row & 7) * 16));
                LDMX4(ah, sb + PAH + off);
                LDMX4(al, sb + PAL + off);
            }
#pragma unroll
            for (int nq = 0; nq < 2; nq++) {
                const int nrow = b_nrow + nq * 16;
                uint32_t off = nrow * 128 + (uint32_t)((kbyte + b_kb) ^ ((nrow & 7) * 16));
                LDMX4(bh[nq], Bh + off);
                LDMX4(bl[nq], Bl + off);
            }
#pragma unroll
            for (int nq = 0; nq < 2; nq++) {
                MMA16816(c[2*nq+0], ah, bh[nq][0], bh[nq][1]);
                MMA16816(c[2*nq+1], ah, bh[nq][2], bh[nq][3]);
                MMA16816(c[2*nq+0], al, bh[nq][0], bh[nq][1]);
                MMA16816(c[2*nq+1], al, bh[nq][2], bh[nq][3]);
                MMA16816(c[2*nq+0], ah, bl[nq][0], bl[nq][1]);
                MMA16816(c[2*nq+1], ah, bl[nq][2], bl[nq][3]);
            }
        }
    }

    // ---- epilogue: +bias, relu, store fp32 ----
    const int row0 = wm * 16 + (lane >> 2);
    const int cb   = wn * 32 + (lane & 3) * 2;
#pragma unroll
    for (int half = 0; half < 2; half++) {
        const int row = row0 + half * 8;
        float2* orow = (float2*)(O + (size_t)(m0 + row) * 256);
#pragma unroll
        for (int nt = 0; nt < 4; nt++) {
            const int col = cb + nt * 8;
            float v0 = fmaxf(c[nt][half * 2 + 0] + bs[col], 0.f);
            float v1 = fmaxf(c[nt][half * 2 + 1] + bs[col + 1], 0.f);
            orow[col >> 1] = make_float2(v0, v1);
        }
    }
}

// ---------------------------------------------------------------------------
// Fused main kernel (unchanged from R5): single fp16 term, 1024 threads.
// ---------------------------------------------------------------------------
#define A_OFF 0
#define B_OFF 65536
#define B_BUF 32768
#define FP_OFF 131072
#define FUSED_SMEM 146432

__global__ __launch_bounds__(1024, 1) void fused_mma_kernel(
    const float* __restrict__ b3, const float* __restrict__ g0,
    const float* __restrict__ be0, const float* __restrict__ g1,
    const float* __restrict__ be1, float* __restrict__ out)
{
    extern __shared__ char smem[];
    const uint32_t sb = smem_u32(smem);
    float* F   = (float*)(smem + FP_OFF);
    float* h1s = F;          float* b3s = F + 256;
    float* g0s = F + 512;    float* e0s = F + 768;
    float* g1s = F + 1024;   float* e1s = F + 1280;
    float* red_s = F + 1536;   // [128][8]
    float* red_q = F + 2560;   // [128][8]
    float* muS   = F + 3584;   // [128]
    float* invS  = F + 3712;   // [128]

    const int tid  = threadIdx.x;
    const int lane = tid & 31;
    const int wid  = tid >> 5;
    const int bn   = blockIdx.x;
    const int b    = bn >> 5;
    const int t0   = blockIdx.y * 128;

#pragma unroll
    for (int i = 0; i < 2; i++) {
        int seg = tid + i * 1024;
        int n = seg >> 3, u = seg & 7;
        uint32_t dst = sb + B_OFF + n * 128 + ((u * 16) ^ ((n & 7) * 16));
        CP_ASYNC16(dst, (const void*)(g_Bh + n * 256 + u * 8));
    }
    CP_COMMIT();

    if (tid < 256) {
        h1s[tid] = g_h1[(size_t)bn * 256 + tid];
        b3s[tid] = b3[tid];
        g0s[tid] = g0[tid];  e0s[tid] = be0[tid];
        g1s[tid] = g1[tid];  e1s[tid] = be1[tid];
    }
    __syncthreads();

#pragma unroll
    for (int rr = 0; rr < 4; rr++) {
        const int r = wid + rr * 32;
        const float4* h2v = (const float4*)(g_h2 + ((size_t)(b * TDIM + t0 + r)) * HH) + lane * 2;
        const float4* h1v = (const float4*)h1s + lane * 2;
        float4 a0 = h1v[0], a1 = h1v[1];
        float4 c0 = h2v[0], c1 = h2v[1];
        float p[8];
        p[0] = a0.x * c0.x; p[1] = a0.y * c0.y; p[2] = a0.z * c0.z; p[3] = a0.w * c0.w;
        p[4] = a1.x * c1.x; p[5] = a1.y * c1.y; p[6] = a1.z * c1.z; p[7] = a1.w * c1.w;
        float s = 0.f, q = 0.f;
#pragma unroll
        for (int j = 0; j < 8; j++) { s += p[j]; q += p[j] * p[j]; }
#pragma unroll
        for (int o = 16; o > 0; o >>= 1) {
            s += __shfl_xor_sync(0xffffffffu, s, o);
            q += __shfl_xor_sync(0xffffffffu, q, o);
        }
        const float mu  = s * (1.f / 256.f);
        const float var = q * (1.f / 256.f) - mu * mu;
        const float inv = rsqrtf(var + EPS);
        float x[8];
#pragma unroll
        for (int j = 0; j < 8; j++)
            x[j] = (p[j] - mu) * inv * g0s[lane * 8 + j] + e0s[lane * 8 + j];
        uint4 wv;
        wv.x = pack_f16x2(x[0], x[1]); wv.y = pack_f16x2(x[2], x[3]);
        wv.z = pack_f16x2(x[4], x[5]); wv.w = pack_f16x2(x[6], x[7]);
        uint32_t unit = ((uint32_t)(lane * 16)) ^ ((uint32_t)(r & 7) * 16u);
        *(uint4*)(smem + A_OFF + r * 512 + unit) = wv;
    }
    __syncthreads();

    const int wm = wid & 3, wn = wid >> 2;
    const int sub = lane >> 3, r8 = lane & 7;
    const int a_row = wm * 32 + r8 + (sub & 1) * 8;
    const int a_kb  = (sub >> 1) * 16;
    const int b_nrow = wn * 32 + r8 + (sub >> 1) * 8;
    const int b_kb  = (sub & 1) * 16;

    float c[2][4][4];
#pragma unroll
    for (int mt = 0; mt < 2; mt++)
#pragma unroll
        for (int nt = 0; nt < 4; nt++)
#pragma unroll
            for (int i = 0; i < 4; i++) c[mt][nt][i] = 0.f;

    for (int ch = 0; ch < 4; ch++) {
        CP_WAIT0();
        __syncthreads();
        if (ch < 3) {
            const int kc2 = (ch + 1) * 64;
            const uint32_t bsd = sb + B_OFF + ((ch + 1) & 1) * B_BUF;
#pragma unroll
            for (int i = 0; i < 2; i++) {
                int seg = tid + i * 1024;
                int n = seg >> 3, u = seg & 7;
                uint32_t dst = bsd + n * 128 + ((u * 16) ^ ((n & 7) * 16));
                CP_ASYNC16(dst, (const void*)(g_Bh + n * 256 + kc2 + u * 8));
            }
            CP_COMMIT();
        }
        const int kcb = ch * 128;
        const uint32_t Bb = sb + B_OFF + (ch & 1) * B_BUF;

#pragma unroll
        for (int ks = 0; ks < 4; ks++) {
            uint32_t bq[2][4], a[2][4];
            const int kbyte = ks * 32;
#pragma unroll
            for (int nq = 0; nq < 2; nq++) {
                const int nrow = b_nrow + nq * 16;
                uint32_t addr = Bb + nrow * 128
                              + (uint32_t)((kbyte + b_kb) ^ ((nrow & 7) * 16));
                LDMX4(bq[nq], addr);
            }
#pragma unroll
            for (int mt = 0; mt < 2; mt++) {
                const int arow = a_row + mt * 16;
                uint32_t addr = sb + A_OFF + arow * 512
                              + (uint32_t)((kcb + kbyte + a_kb) ^ ((arow & 7) * 16));
                LDMX4(a[mt], addr);
            }
#pragma unroll
            for (int mt = 0; mt < 2; mt++)
#pragma unroll
                for (int nq = 0; nq < 2; nq++) {
                    MMA16816(c[mt][2 * nq + 0], a[mt], bq[nq][0], bq[nq][1]);
                    MMA16816(c[mt][2 * nq + 1], a[mt], bq[nq][2], bq[nq][3]);
                }
        }
    }
    __syncthreads();

    const int rbase = wm * 32 + (lane >> 2);
    const int cbase = wn * 32 + (lane & 3) * 2;

    float s[4], q[4];
#pragma unroll
    for (int mt = 0; mt < 2; mt++)
#pragma unroll
        for (int half = 0; half < 2; half++) {
            float ss = 0.f, qq = 0.f;
#pragma unroll
            for (int nt = 0; nt < 4; nt++) {
                int col = cbase + nt * 8;
                float v0 = c[mt][nt][half * 2 + 0] + b3s[col];
                float v1 = c[mt][nt][half * 2 + 1] + b3s[col + 1];
                c[mt][nt][half * 2 + 0] = v0;
                c[mt][nt][half * 2 + 1] = v1;
                ss += v0 + v1; qq += v0 * v0 + v1 * v1;
            }
            s[mt * 2 + half] = ss; q[mt * 2 + half] = qq;
        }
#pragma unroll
    for (int i = 0; i < 4; i++) {
        s[i] += __shfl_xor_sync(0xffffffffu, s[i], 1);
        s[i] += __shfl_xor_sync(0xffffffffu, s[i], 2);
        q[i] += __shfl_xor_sync(0xffffffffu, q[i], 1);
        q[i] += __shfl_xor_sync(0xffffffffu, q[i], 2);
    }
    if ((lane & 3) == 0) {
#pragma unroll
        for (int mt = 0; mt < 2; mt++)
#pragma unroll
            for (int half = 0; half < 2; half++) {
                int row = rbase + mt * 16 + half * 8;
                red_s[row * 8 + wn] = s[mt * 2 + half];
                red_q[row * 8 + wn] = q[mt * 2 + half];
            }
    }
    __syncthreads();
    if (tid < 128) {
        float ss = 0.f, qq = 0.f;
#pragma unroll
        for (int i = 0; i < 8; i++) { ss += red_s[tid * 8 + i]; qq += red_q[tid * 8 + i]; }
        float mu = ss * (1.f / 256.f);
        float var = qq * (1.f / 256.f) - mu * mu;
        muS[tid]  = mu;
        invS[tid] = rsqrtf(var + EPS);
    }
    __syncthreads();

#pragma unroll
    for (int mt = 0; mt < 2; mt++)
#pragma unroll
        for (int half = 0; half < 2; half++) {
            int row = rbase + mt * 16 + half * 8;
            float mu = muS[row], inv = invS[row];
            float2* orow = (float2*)(out + ((size_t)(bn * TDIM + t0 + row)) * HH);
#pragma unroll
            for (int nt = 0; nt < 4; nt++) {
                int col = cbase + nt * 8;
                float o0 = fmaxf((c[mt][nt][half * 2 + 0] - mu) * inv * g1s[col] + e1s[col], 0.f);
                float o1 = fmaxf((c[mt][nt][half * 2 + 1] - mu) * inv * g1s[col + 1] + e1s[col + 1], 0.f);
                orow[col >> 1] = make_float2(o0, o1);
            }
        }
}

// ---------------------------------------------------------------------------
extern "C" void kernel_launch(void* const* d_in, const int* in_sizes, int n_in,
                              void* d_out, int out_size)
{
    const float* x1  = (const float*)d_in[0];
    const float* x2  = (const float*)d_in[1];
    const float* W1  = (const float*)d_in[2];
    const float* b1  = (const float*)d_in[3];
    const float* W2  = (const float*)d_in[4];
    const float* b2  = (const float*)d_in[5];
    const float* W3  = (const float*)d_in[6];
    const float* b3  = (const float*)d_in[7];
    const float* g0  = (const float*)d_in[8];
    const float* be0 = (const float*)d_in[9];
    const float* g1  = (const float*)d_in[10];
    const float* be1 = (const float*)d_in[11];
    float* out = (float*)d_out;

    static int attr_set = 0;
    if (!attr_set) {
        cudaFuncSetAttribute(fused_mma_kernel,
                             cudaFuncAttributeMaxDynamicSharedMemorySize, FUSED_SMEM);
        cudaFuncSetAttribute(tc_prologue,
                             cudaFuncAttributeMaxDynamicSharedMemorySize, PROLOGUE_SMEM);
        attr_set = 1;
    }

    prep_kernel<<<320, 256>>>(W1, W2, W3);
    tc_prologue<<<144, 512, PROLOGUE_SMEM>>>(x1, b1, x2, b2);

    dim3 grid(BB * NN, 2);
    fused_mma_kernel<<<grid, 1024, FUSED_SMEM>>>(b3, g0, be0, g1, be1, out);
}